// round 2
// baseline (speedup 1.0000x reference)
#include <cuda_runtime.h>
#include <math.h>

// Problem: x (4096, 8192) f32 row-major, a scalar f32.
// z = -exp(a) * x ; out = sparsemax(z, axis=0)  (per-column simplex projection)
//
// R2: 1024 threads/block (32 warps, 50% occ) with 32 floats/thread in regs.
// Block = 8 columns x 4096 rows (128KB), loaded once via float4, held in
// registers. Per-column max via parity shuffles + shared; support candidates
// {z - max > -1} pushed to shared; tau via bisection + Michelot (exact);
// output streamed back from registers. Data touched exactly once each way.

#define THREADS 1024
#define NWARPS  (THREADS / 32)
#define COLS    8
#define WIDTH   8192
#define ROWS    4096
#define NV4     8         // float4 loads per thread -> 32 floats
#define CAP     256       // candidate buffer per column (expected count ~3-40)

__global__ __launch_bounds__(THREADS, 1)
void sparsemax_cols_kernel(const float* __restrict__ x,
                           const float* __restrict__ a,
                           float* __restrict__ out)
{
    __shared__ float s_wmax[NWARPS][COLS];
    __shared__ float s_colmax[COLS];
    __shared__ float s_thr[COLS];
    __shared__ int   s_cnt[COLS];
    __shared__ float s_buf[COLS][CAP];

    const int tid  = threadIdx.x;
    const int lane = tid & 31;
    const int warp = tid >> 5;
    const int q    = tid & 1;           // parity: q=0 -> local cols 0..3, q=1 -> 4..7
    const int c0   = blockIdx.x * COLS; // global column base

    if (tid < COLS) s_cnt[tid] = 0;

    const float scale = -expf(a[0]);

    // ---- load: 8 float4 per thread; z = scale * x ----
    float v[NV4][4];
#pragma unroll
    for (int j = 0; j < NV4; ++j) {
        int f   = tid + j * THREADS;        // flat float4 index in tile
        int row = f >> 1;                   // (f & 1) == q since THREADS is even
        const float4* p = reinterpret_cast<const float4*>(
            x + (size_t)row * WIDTH + c0 + 4 * q);
        float4 t = *p;
        v[j][0] = scale * t.x;
        v[j][1] = scale * t.y;
        v[j][2] = scale * t.z;
        v[j][3] = scale * t.w;
    }

    // ---- per-column max ----
    float m[4] = {-INFINITY, -INFINITY, -INFINITY, -INFINITY};
#pragma unroll
    for (int j = 0; j < NV4; ++j) {
#pragma unroll
        for (int c = 0; c < 4; ++c) m[c] = fmaxf(m[c], v[j][c]);
    }
    // reduce among same-parity lanes (xor by even offsets keeps parity)
#pragma unroll
    for (int off = 2; off <= 16; off <<= 1) {
#pragma unroll
        for (int c = 0; c < 4; ++c)
            m[c] = fmaxf(m[c], __shfl_xor_sync(0xffffffffu, m[c], off));
    }
    if (lane < 2) {
#pragma unroll
        for (int c = 0; c < 4; ++c) s_wmax[warp][lane * 4 + c] = m[c];
    }
    __syncthreads();
    if (tid < COLS) {
        float mm = s_wmax[0][tid];
#pragma unroll
        for (int w = 1; w < NWARPS; ++w) mm = fmaxf(mm, s_wmax[w][tid]);
        s_colmax[tid] = mm;
    }
    __syncthreads();

    // ---- shift by column max; collect candidates z' > -1 ----
    float cm[4];
#pragma unroll
    for (int c = 0; c < 4; ++c) cm[c] = s_colmax[4 * q + c];

#pragma unroll
    for (int j = 0; j < NV4; ++j) {
#pragma unroll
        for (int c = 0; c < 4; ++c) {
            float zp = v[j][c] - cm[c];
            v[j][c] = zp;
            if (zp > -1.0f) {
                int col = 4 * q + c;
                int pos = atomicAdd(&s_cnt[col], 1);
                if (pos < CAP) s_buf[col][pos] = zp;
            }
        }
    }
    __syncthreads();

    // ---- solve tau per column (1 thread per column) ----
    if (tid < COLS) {
        int n = s_cnt[tid];
        if (n > CAP) n = CAP;
        const float* b = s_buf[tid];

        // bisection: tau* in (-1, 0); g(tau) = sum max(z'-tau,0) - 1, decreasing
        float lo = -1.0f, hi = 0.0f;
        for (int it = 0; it < 14; ++it) {
            float mid = 0.5f * (lo + hi);
            float g = -1.0f;
            for (int i = 0; i < n; ++i) g += fmaxf(b[i] - mid, 0.0f);
            if (g > 0.0f) lo = mid; else hi = mid;
        }
        // Michelot fixed point from below (lo <= tau*): exact at convergence
        float tau = lo;
        for (int it = 0; it < 16; ++it) {
            float ssum = 0.0f;
            int   k    = 0;
            for (int i = 0; i < n; ++i) {
                float z = b[i];
                if (z > tau) { ssum += z; ++k; }
            }
            float tn = (ssum - 1.0f) / (float)k;   // k >= 1 (z'=0 > tau < 0)
            if (tn == tau) break;
            tau = tn;
        }
        s_thr[tid] = tau;
    }
    __syncthreads();

    // ---- output: max(z' - tau, 0) ----
    float th[4];
#pragma unroll
    for (int c = 0; c < 4; ++c) th[c] = s_thr[4 * q + c];

#pragma unroll
    for (int j = 0; j < NV4; ++j) {
        int f   = tid + j * THREADS;
        int row = f >> 1;
        float4 o;
        o.x = fmaxf(v[j][0] - th[0], 0.0f);
        o.y = fmaxf(v[j][1] - th[1], 0.0f);
        o.z = fmaxf(v[j][2] - th[2], 0.0f);
        o.w = fmaxf(v[j][3] - th[3], 0.0f);
        *reinterpret_cast<float4*>(out + (size_t)row * WIDTH + c0 + 4 * q) = o;
    }
}

extern "C" void kernel_launch(void* const* d_in, const int* in_sizes, int n_in,
                              void* d_out, int out_size)
{
    const float* x = (const float*)d_in[0];
    const float* a = (const float*)d_in[1];
    float* out     = (float*)d_out;

    dim3 grid(WIDTH / COLS);   // 1024 blocks, 8 columns each
    dim3 block(THREADS);
    sparsemax_cols_kernel<<<grid, block>>>(x, a, out);
}

// round 3
// speedup vs baseline: 1.3945x; 1.3945x over previous
#include <cuda_runtime.h>
#include <math.h>

// Problem: x (4096, 8192) f32 row-major, a scalar f32.
// z = -exp(a) * x ; out = sparsemax(z, axis=0)  (per-column simplex projection)
//
// R3: two perfectly-coalesced streaming kernels (every LDG.128/STG.128 covers
// exactly 4 full 128B lines), 384MB total traffic:
//   K1: per-column max over 128-row chunks -> static partial array (128MB read)
//   K2: 32-col blocks (256 blocks, all resident in 1 wave): reduce partials,
//       stream z once writing ZEROS to out (correct for non-support), collect
//       support candidates {z - max > -1} (+row idx) in shared, solve tau
//       exactly (bisection + Michelot), scatter the few support values.

#define WIDTH 8192
#define ROWS  4096
#define NCHUNK 32          // 4096 / 128 row-chunks
#define CAP   128          // candidate buffer per column (expected ~5-20)

__device__ float g_part[NCHUNK][WIDTH];   // per-chunk column maxima of z

// ---------------- K1: partial column max ----------------
__global__ __launch_bounds__(256)
void colmax_kernel(const float* __restrict__ x, const float* __restrict__ a)
{
    const float scale = -expf(a[0]);
    const int c  = blockIdx.x * 1024 + threadIdx.x * 4;  // 8 stripes x 1024 cols
    const int r0 = blockIdx.y * 128;                     // 32 row chunks

    const float4* p = reinterpret_cast<const float4*>(x + (size_t)r0 * WIDTH + c);
    float m0 = -INFINITY, m1 = -INFINITY, m2 = -INFINITY, m3 = -INFINITY;

#pragma unroll 8
    for (int r = 0; r < 128; ++r) {
        float4 t = p[(size_t)r * (WIDTH / 4)];
        m0 = fmaxf(m0, scale * t.x);
        m1 = fmaxf(m1, scale * t.y);
        m2 = fmaxf(m2, scale * t.z);
        m3 = fmaxf(m3, scale * t.w);
    }
    *reinterpret_cast<float4*>(&g_part[blockIdx.y][c]) = make_float4(m0, m1, m2, m3);
}

// ---------------- K2: candidates + tau + output ----------------
__global__ __launch_bounds__(512, 2)
void sparsemax_out_kernel(const float* __restrict__ x,
                          const float* __restrict__ a,
                          float* __restrict__ out)
{
    __shared__ float s_red[16][32];
    __shared__ float s_cmax[32];
    __shared__ float s_tau[32];
    __shared__ int   s_cnt[32];
    __shared__ float s_bv[32][CAP];
    __shared__ int   s_br[32][CAP];

    const int tid  = threadIdx.x;
    const int lane = tid & 31;
    const int warp = tid >> 5;
    const int c0   = blockIdx.x * 32;
    const float scale = -expf(a[0]);

    if (tid < 32) s_cnt[tid] = 0;

    // reduce 32 partial maxima per column
    if (warp < 16) {
        float v = fmaxf(g_part[warp][c0 + lane], g_part[warp + 16][c0 + lane]);
        s_red[warp][lane] = v;
    }
    __syncthreads();
    if (tid < 32) {
        float m = s_red[0][tid];
#pragma unroll
        for (int j = 1; j < 16; ++j) m = fmaxf(m, s_red[j][tid]);
        s_cmax[tid] = m;
    }
    __syncthreads();

    // stream: warp = 4 rows x 32 cols = 4 full 128B lines per LDG/STG
    const int col4  = tid & 7;    // float4 slot within the 32-col stripe
    const int rbase = tid >> 3;   // 0..63
    float cm[4];
#pragma unroll
    for (int c = 0; c < 4; ++c) cm[c] = s_cmax[col4 * 4 + c];

    const float4 zero4 = make_float4(0.f, 0.f, 0.f, 0.f);

    for (int i = 0; i < 64; i += 4) {
        float4 t[4];
        int    rw[4];
#pragma unroll
        for (int u = 0; u < 4; ++u) {
            rw[u] = rbase + (i + u) * 64;
            t[u] = *(reinterpret_cast<const float4*>(x + (size_t)rw[u] * WIDTH + c0) + col4);
        }
#pragma unroll
        for (int u = 0; u < 4; ++u) {
            float zs[4];
            zs[0] = scale * t[u].x - cm[0];
            zs[1] = scale * t[u].y - cm[1];
            zs[2] = scale * t[u].z - cm[2];
            zs[3] = scale * t[u].w - cm[3];
            // zeros are the correct final value for every non-support element
            *(reinterpret_cast<float4*>(out + (size_t)rw[u] * WIDTH + c0) + col4) = zero4;
#pragma unroll
            for (int c = 0; c < 4; ++c) {
                if (zs[c] > -1.0f) {                      // tau >= max-1 always
                    int col = col4 * 4 + c;
                    int pos = atomicAdd(&s_cnt[col], 1);
                    if (pos < CAP) { s_bv[col][pos] = zs[c]; s_br[col][pos] = rw[u]; }
                }
            }
        }
    }
    __syncthreads();

    // solve tau per column: 14 bisections on (-1,0), then exact Michelot
    if (tid < 32) {
        int n = min(s_cnt[tid], CAP);
        const float* b = s_bv[tid];
        float lo = -1.0f, hi = 0.0f;
        for (int it = 0; it < 14; ++it) {
            float mid = 0.5f * (lo + hi);
            float g = -1.0f;
            for (int k = 0; k < n; ++k) g += fmaxf(b[k] - mid, 0.0f);
            if (g > 0.0f) lo = mid; else hi = mid;
        }
        float tau = lo;
        for (int it = 0; it < 16; ++it) {
            float s = 0.0f; int k = 0;
            for (int j = 0; j < n; ++j) {
                float z = b[j];
                if (z > tau) { s += z; ++k; }
            }
            float tn = (s - 1.0f) / (float)k;   // k >= 1 since zs_max = 0 > tau
            if (tn == tau) break;
            tau = tn;
        }
        s_tau[tid] = tau;
    }
    __syncthreads();

    // scatter support values (tiny)
    {
        const int col = tid & 31;
        const int st  = tid >> 5;   // 0..15
        float tau = s_tau[col];
        int n = min(s_cnt[col], CAP);
        for (int j = st; j < n; j += 16) {
            float v = s_bv[col][j] - tau;
            if (v > 0.0f) out[(size_t)s_br[col][j] * WIDTH + c0 + col] = v;
        }
    }
}

extern "C" void kernel_launch(void* const* d_in, const int* in_sizes, int n_in,
                              void* d_out, int out_size)
{
    const float* x = (const float*)d_in[0];
    const float* a = (const float*)d_in[1];
    float* out     = (float*)d_out;

    colmax_kernel<<<dim3(8, 32), 256>>>(x, a);
    sparsemax_out_kernel<<<WIDTH / 32, 512>>>(x, a, out);
}

// round 4
// speedup vs baseline: 1.5652x; 1.1224x over previous
#include <cuda_runtime.h>
#include <math.h>

// z = -exp(a) * x ; out = sparsemax(z, axis=0), x (4096, 8192) f32 row-major.
//
// R4: single fused kernel. Block owns a 32-col x 4096-row stripe (512KB):
//   phase A: stream stripe, per-column max (loads allocate in L2)
//   phase B: re-stream stripe FROM L2 (__ldcs), write zeros to out (__stcs,
//            correct value for all non-support rows), collect candidates
//            {z - max > -1} into shared (tau >= max-1 always)
//   solve tau exactly (14 bisections on (-1,0) + Michelot fixed point)
//   scatter the few support values.
// grid=128, 1024 thr: 1 block/SM, live x set = 64MB < 126MB L2 -> x hits DRAM
// exactly once. Every LDG.128/STG.128 covers 4 full 128B lines.

#define WIDTH   8192
#define ROWS    4096
#define NSTRIPE 256        // 8192 / 32 columns
#define THREADS 1024
#define NWARPS  32
#define CAP     128        // candidates per column (expected ~5-40)

__global__ __launch_bounds__(THREADS, 1)
void sparsemax_fused_kernel(const float* __restrict__ x,
                            const float* __restrict__ a,
                            float* __restrict__ out)
{
    __shared__ float s_wm[NWARPS][32];
    __shared__ float s_cmax[32];
    __shared__ float s_tau[32];
    __shared__ int   s_cnt[32];
    __shared__ float s_bv[32][CAP];
    __shared__ int   s_br[32][CAP];

    const int tid   = threadIdx.x;
    const int lane  = tid & 31;
    const int warp  = tid >> 5;
    const int col4  = tid & 7;     // float4 slot within 32-col stripe
    const int rbase = tid >> 3;    // 0..127
    const float scale = -expf(a[0]);

    for (int s = blockIdx.x; s < NSTRIPE; s += gridDim.x) {
        const int c0 = s * 32;
        const float4* xp = reinterpret_cast<const float4*>(x + c0) + col4;
        float4*       op = reinterpret_cast<float4*>(out + c0) + col4;

        if (tid < 32) s_cnt[tid] = 0;

        // ---- phase A: per-column max (warp covers 4 rows x 128B lines) ----
        float m0 = -INFINITY, m1 = -INFINITY, m2 = -INFINITY, m3 = -INFINITY;
#pragma unroll 4
        for (int i = 0; i < 32; ++i) {
            float4 t = xp[(size_t)(rbase + i * 128) * (WIDTH / 4)];
            m0 = fmaxf(m0, scale * t.x);
            m1 = fmaxf(m1, scale * t.y);
            m2 = fmaxf(m2, scale * t.z);
            m3 = fmaxf(m3, scale * t.w);
        }
        // lanes {l, l+8, l+16, l+24} share col4 -> reduce via xor 8,16
#pragma unroll
        for (int off = 8; off <= 16; off <<= 1) {
            m0 = fmaxf(m0, __shfl_xor_sync(0xffffffffu, m0, off));
            m1 = fmaxf(m1, __shfl_xor_sync(0xffffffffu, m1, off));
            m2 = fmaxf(m2, __shfl_xor_sync(0xffffffffu, m2, off));
            m3 = fmaxf(m3, __shfl_xor_sync(0xffffffffu, m3, off));
        }
        if (lane < 8) {
            s_wm[warp][lane * 4 + 0] = m0;
            s_wm[warp][lane * 4 + 1] = m1;
            s_wm[warp][lane * 4 + 2] = m2;
            s_wm[warp][lane * 4 + 3] = m3;
        }
        __syncthreads();
        if (tid < 32) {
            float mm = s_wm[0][tid];
#pragma unroll
            for (int w = 1; w < NWARPS; ++w) mm = fmaxf(mm, s_wm[w][tid]);
            s_cmax[tid] = mm;
        }
        __syncthreads();

        float cm[4];
#pragma unroll
        for (int c = 0; c < 4; ++c) cm[c] = s_cmax[col4 * 4 + c];

        // ---- phase B: re-stream from L2, write zeros, collect candidates ----
        const float4 zero4 = make_float4(0.f, 0.f, 0.f, 0.f);
        for (int i = 0; i < 32; i += 4) {
            float4 t[4];
            int    rw[4];
#pragma unroll
            for (int u = 0; u < 4; ++u) {
                rw[u] = rbase + (i + u) * 128;
                t[u]  = __ldcs(&xp[(size_t)rw[u] * (WIDTH / 4)]);   // last use
            }
#pragma unroll
            for (int u = 0; u < 4; ++u) {
                float zs[4];
                zs[0] = scale * t[u].x - cm[0];
                zs[1] = scale * t[u].y - cm[1];
                zs[2] = scale * t[u].z - cm[2];
                zs[3] = scale * t[u].w - cm[3];
                __stcs(&op[(size_t)rw[u] * (WIDTH / 4)], zero4);    // streaming
#pragma unroll
                for (int c = 0; c < 4; ++c) {
                    if (zs[c] > -1.0f) {
                        int col = col4 * 4 + c;
                        int pos = atomicAdd(&s_cnt[col], 1);
                        if (pos < CAP) { s_bv[col][pos] = zs[c]; s_br[col][pos] = rw[u]; }
                    }
                }
            }
        }
        __syncthreads();

        // ---- tau per column: 14 bisections on (-1,0), then exact Michelot ----
        if (tid < 32) {
            int n = min(s_cnt[tid], CAP);
            const float* b = s_bv[tid];
            float lo = -1.0f, hi = 0.0f;
            for (int it = 0; it < 14; ++it) {
                float mid = 0.5f * (lo + hi);
                float g = -1.0f;
                for (int k = 0; k < n; ++k) g += fmaxf(b[k] - mid, 0.0f);
                if (g > 0.0f) lo = mid; else hi = mid;
            }
            float tau = lo;
            for (int it = 0; it < 16; ++it) {
                float sum = 0.0f; int k = 0;
                for (int j = 0; j < n; ++j) {
                    float z = b[j];
                    if (z > tau) { sum += z; ++k; }
                }
                float tn = (sum - 1.0f) / (float)k;   // k >= 1 (zs_max = 0 > tau)
                if (tn == tau) break;
                tau = tn;
            }
            s_tau[tid] = tau;
        }
        __syncthreads();

        // ---- scatter support values ----
        {
            const int col = tid & 31;
            const int st  = tid >> 5;     // 0..31
            float tau = s_tau[col];
            int n = min(s_cnt[col], CAP);
            for (int j = st; j < n; j += 32) {
                float v = s_bv[col][j] - tau;
                if (v > 0.0f) out[(size_t)s_br[col][j] * WIDTH + c0 + col] = v;
            }
        }
        __syncthreads();   // protect s_cnt/s_bv before next stripe
    }
}

extern "C" void kernel_launch(void* const* d_in, const int* in_sizes, int n_in,
                              void* d_out, int out_size)
{
    const float* x = (const float*)d_in[0];
    const float* a = (const float*)d_in[1];
    float* out     = (float*)d_out;

    sparsemax_fused_kernel<<<128, THREADS>>>(x, a, out);   // 2 stripes per block
}